// round 16
// baseline (speedup 1.0000x reference)
#include <cuda_runtime.h>
#include <cuda_bf16.h>
#include <math.h>

// Problem constants
#define B    512
#define T    365
#define INP  10
#define H    256
#define OUT  20

// 4 batch groups (128 rows) x 32 column groups (8 cols) = 128 persistent CTAs,
// 256 thr = 8 warps; warp w = M-tile (16 rows). Warp-granular dataflow with
// FINE-GRAINED per-kstep polling pipelined into the mma stream, 9-chain
// product-round-interleaved mma order, depth-2 A-frag LDG pipeline.
#define GB        4
#define GC        32
#define NCTA      (GB * GC)
#define NTHREADS  256

// A-fragment arrays: [buf2][gb4][mtile8][kstep16][split2][lane32] x uint4
#define HA_ELEMS  (2 * 4 * 8 * 16 * 2 * 32)

__device__ uint4 g_hA0[HA_ELEMS];
__device__ uint4 g_hA1[HA_ELEMS];
__device__ float g_hfin[B * H];
// Publish counters: [gb][mt][16 ks + 16 pad] -> one 128B line per (gb,mt).
__device__ __align__(128) unsigned g_cnt0[GB][8][32];
__device__ __align__(128) unsigned g_cnt1[GB][8][32];
__device__ unsigned g_cnt_all;
__device__ unsigned g_gen_all;

__device__ __forceinline__ int ha_idx(int buf, int gb, int mt, int ks, int sp, int l) {
    return (((((buf * 4 + gb) * 8 + mt) * 16 + ks) * 2 + sp) * 32 + l);
}

__device__ __forceinline__ void barrier_sync(unsigned* cnt, unsigned* gen, unsigned target) {
    __threadfence();
    __syncthreads();
    if (threadIdx.x == 0) {
        unsigned g = *(volatile unsigned*)gen;
        if (atomicAdd(cnt, 1u) == target - 1u) {
            *cnt = 0u;
            __threadfence();
            atomicAdd(gen, 1u);
        } else {
            while (*(volatile unsigned*)gen == g) { }
        }
    }
    __syncthreads();
}

// Fine-grained poll for ONE kstep: even lanes watch C0[ks] (target t0),
// odd lanes watch C1[ks] (target t1). Exits when both satisfied.
__device__ __forceinline__ void poll_ks(const unsigned* c0, const unsigned* c1,
                                        int ks, unsigned t0, unsigned t1, int l) {
    const unsigned* p = (l & 1) ? (c1 + ks) : (c0 + ks);
    const unsigned tgt = (l & 1) ? t1 : t0;
    unsigned v;
    do {
        asm volatile("ld.acquire.gpu.global.u32 %0, [%1];" : "=r"(v) : "l"(p) : "memory");
    } while (!__all_sync(0xffffffffu, v >= tgt));
}

// Producer publish: fence own stores, warp-converge, lane0 RED +1.
__device__ __forceinline__ void publish_cnt(unsigned* cnt, int l) {
    __threadfence();
    __syncwarp();
    if (l == 0) atomicAdd(cnt, 1u);
}

// mma.sync m16n8k16 row.col f32.bf16.bf16.f32, accumulate in place.
__device__ __forceinline__ void mma_bf16(float* d, unsigned a0, unsigned a1,
                                         unsigned a2, unsigned a3,
                                         unsigned b0, unsigned b1) {
    asm volatile(
        "mma.sync.aligned.m16n8k16.row.col.f32.bf16.bf16.f32 "
        "{%0,%1,%2,%3}, {%4,%5,%6,%7}, {%8,%9}, {%0,%1,%2,%3};"
        : "+f"(d[0]), "+f"(d[1]), "+f"(d[2]), "+f"(d[3])
        : "r"(a0), "r"(a1), "r"(a2), "r"(a3), "r"(b0), "r"(b1));
}

// Split two fp32 into packed bf16x2 (hi) + packed bf16x2 (lo residual).
__device__ __forceinline__ void split2(float a, float b, unsigned& hi, unsigned& lo) {
    __nv_bfloat16 ah = __float2bfloat16_rn(a), bh = __float2bfloat16_rn(b);
    __nv_bfloat16 al = __float2bfloat16_rn(a - __bfloat162float(ah));
    __nv_bfloat16 bl = __float2bfloat16_rn(b - __bfloat162float(bh));
    __nv_bfloat162 h2; h2.x = ah; h2.y = bh;
    __nv_bfloat162 l2; l2.x = al; l2.y = bl;
    hi = *reinterpret_cast<unsigned*>(&h2);
    lo = *reinterpret_cast<unsigned*>(&l2);
}

// Fast gate math (MUFU-based; ~1e-6 error vs 1e-3 tolerance).
__device__ __forceinline__ float fsig(float v) {
    return 1.0f / (1.0f + __expf(-v));
}
__device__ __forceinline__ float ftanh_(float v) {
    return 2.0f / (1.0f + __expf(-2.0f * v)) - 1.0f;
}

// Weight frags: sets s (0=hh0, 1=hh1, 2=ih1) x 3 ntiles x 16 ksteps x 32 lanes,
// uint4 = {b0_hi, b1_hi, b0_lo, b1_lo}. 4608 x 16B = 72 KB.
#define NWB (3 * 3 * 16 * 32)

__global__ void __launch_bounds__(NTHREADS, 1)
gru_tc_kernel(const float* __restrict__ x,
              const float* __restrict__ W_ih0, const float* __restrict__ W_hh0,
              const float* __restrict__ b_ih0, const float* __restrict__ b_hh0,
              const float* __restrict__ W_ih1, const float* __restrict__ W_hh1,
              const float* __restrict__ b_ih1, const float* __restrict__ b_hh1,
              const float* __restrict__ W_out, const float* __restrict__ b_out,
              float* __restrict__ out) {
    extern __shared__ char smraw[];
    uint4* sWB  = reinterpret_cast<uint4*>(smraw);     // NWB x 16B
    float* sx   = reinterpret_cast<float*>(sWB + NWB); // 8 warps x 192
    float* sWi0 = sx + 8 * 192;                        // 24*12
    float* sBi0 = sWi0 + 24 * 12;                      // 24 each
    float* sBh0 = sBi0 + 24;
    float* sBi1 = sBh0 + 24;
    float* sBh1 = sBi1 + 24;

    const int tid = threadIdx.x;
    const int w   = tid >> 5;              // warp = M-tile 0..7
    const int l   = tid & 31;              // lane
    const int g   = l >> 2;                // frag row group 0..7
    const int c   = l & 3;                 // frag col pair 0..3
    const int gb  = blockIdx.x >> 5;       // batch group
    const int gc  = blockIdx.x & 31;       // column group
    const int c0  = gc * 8;
    const int gb0 = gb * 128;
    const int ksW = gc >> 1;               // kstep our h-cols land in
    const int wboff = 8 * (gc & 1);        // byte offset within 16B frag slot

    unsigned* myCnt0 = &g_cnt0[gb][w][ksW];
    unsigned* myCnt1 = &g_cnt1[gb][w][ksW];
    const unsigned* pollC0 = &g_cnt0[gb][w][0];
    const unsigned* pollC1 = &g_cnt1[gb][w][0];

    // ---- Prologue: pack weights into B-fragment layout (hi/lo split) ----
    {
        const float* Wsets[3] = { W_hh0, W_hh1, W_ih1 };
        for (int e = tid; e < NWB; e += NTHREADS) {
            int lane = e & 31;
            int ks   = (e >> 5) & 15;
            int rest = e >> 9;
            int n    = rest % 3;
            int s    = rest / 3;
            int t4 = lane & 3, nn = lane >> 2;
            const float* Wp = Wsets[s] + (size_t)(n * H + c0 + nn) * H + ks * 16;
            float w00 = Wp[2 * t4],     w01 = Wp[2 * t4 + 1];
            float w10 = Wp[8 + 2 * t4], w11 = Wp[9 + 2 * t4];
            uint4 v;
            split2(w00, w01, v.x, v.z);
            split2(w10, w11, v.y, v.w);
            sWB[e] = v;
        }
    }
    for (int idx = tid; idx < 24 * INP; idx += NTHREADS) {
        int row = idx / INP, i = idx - row * INP;
        int gg = row >> 3, j = row & 7;
        sWi0[row * 12 + i] = W_ih0[(gg * H + c0 + j) * INP + i];
    }
    if (tid < 24) {
        int gg = tid >> 3, j = tid & 7;
        int grow = gg * H + c0 + j;
        sBi0[tid] = b_ih0[grow];
        sBh0[tid] = b_hh0[grow];
        sBi1[tid] = b_ih1[grow];
        sBh1[tid] = b_hh1[grow];
    }

    // Zero A-frag buffers + counters; every launch (determinism).
    {
        uint4 z4 = make_uint4(0u, 0u, 0u, 0u);
        for (int i = blockIdx.x * NTHREADS + tid; i < HA_ELEMS; i += NCTA * NTHREADS) {
            g_hA0[i] = z4;
            g_hA1[i] = z4;
        }
        unsigned* c0p = &g_cnt0[0][0][0];
        unsigned* c1p = &g_cnt1[0][0][0];
        for (int i = blockIdx.x * NTHREADS + tid; i < GB * 8 * 32; i += NCTA * NTHREADS) {
            c0p[i] = 0u;
            c1p[i] = 0u;
        }
    }
    barrier_sync(&g_cnt_all, &g_gen_all, NCTA);

    // Per-thread persistent hidden state (4 D-frag positions).
    float h0reg[4] = {0.f, 0.f, 0.f, 0.f};
    float h1reg[4] = {0.f, 0.f, 0.f, 0.f};

    // ---- Warp-autonomous loop: iter i computes h0[i] and h1[i-1]. ----
    for (int i = 0; i <= T; ++i) {
        const int bufR = i & 1, bufW = bufR ^ 1;
        const unsigned t0 = 2u * (unsigned)i;
        const unsigned t1 = (i >= 1) ? 2u * (unsigned)(i - 1) : 0u;

        // Stage x[i] + x-projection BEFORE any waits (h-independent).
        float xp[12];
        if (i < T) {
            float* sxw = sx + w * 192;
            for (int e = l; e < 16 * INP; e += 32) {
                int row = e / INP, k = e - row * INP;
                sxw[row * 12 + k] =
                    __ldg(&x[((size_t)(gb0 + w * 16 + row) * T + i) * INP + k]);
            }
            __syncwarp();
#pragma unroll
            for (int p = 0; p < 4; ++p) {
                int lrow = g + 8 * (p >> 1);
                int jc = 2 * c + (p & 1);
                float xr = 0.f, xz = 0.f, xn = 0.f;
#pragma unroll
                for (int k = 0; k < INP; ++k) {
                    float xv = sxw[lrow * 12 + k];
                    xr += xv * sWi0[(0 * 8 + jc) * 12 + k];
                    xz += xv * sWi0[(1 * 8 + jc) * 12 + k];
                    xn += xv * sWi0[(2 * 8 + jc) * 12 + k];
                }
                xp[p] = xr; xp[4 + p] = xz; xp[8 + p] = xn;
            }
        }

        // ===== Single merged mma stream with PER-KSTEP polls pipelined in.
        // acc [0..2]=hh0, [3..5]=hh1, [6..8]=ih1. Same-acc distance = 9 mma.
        float acc[9][4] = {};
        {
            const uint4* pA0 = g_hA0 + ha_idx(bufR, gb, w, 0, 0, 0);
            const uint4* pA1 = g_hA1 + ha_idx(bufR, gb, w, 0, 0, 0);
            // Depth-2 LDG pipeline, 3-slot register ring; poll ks before its LDG.
            uint4 rA0h[3], rA0l[3], rA1h[3], rA1l[3];
#pragma unroll
            for (int pld = 0; pld < 2; ++pld) {
                poll_ks(pollC0, pollC1, pld, t0, t1, l);
                rA0h[pld] = __ldcg(pA0 + pld * 64 + l);
                rA0l[pld] = __ldcg(pA0 + pld * 64 + 32 + l);
                rA1h[pld] = __ldcg(pA1 + pld * 64 + l);
                rA1l[pld] = __ldcg(pA1 + pld * 64 + 32 + l);
            }
#pragma unroll
            for (int ks = 0; ks < 16; ++ks) {
                const int cur = ks % 3;
                if (ks + 2 < 16) {
                    const int nx = (ks + 2) % 3;
                    poll_ks(pollC0, pollC1, ks + 2, t0, t1, l);
                    rA0h[nx] = __ldcg(pA0 + (ks + 2) * 64 + l);
                    rA0l[nx] = __ldcg(pA0 + (ks + 2) * 64 + 32 + l);
                    rA1h[nx] = __ldcg(pA1 + (ks + 2) * 64 + l);
                    rA1l[nx] = __ldcg(pA1 + (ks + 2) * 64 + 32 + l);
                }
                uint4 w0[3], w1[3], w2[3];
#pragma unroll
                for (int n = 0; n < 3; ++n) {
                    w0[n] = sWB[((0 * 3 + n) * 16 + ks) * 32 + l];
                    w1[n] = sWB[((1 * 3 + n) * 16 + ks) * 32 + l];
                    w2[n] = sWB[((2 * 3 + n) * 16 + ks) * 32 + l];
                }
                const uint4 a0h = rA0h[cur], a0l = rA0l[cur];
                const uint4 a1h = rA1h[cur], a1l = rA1l[cur];
                // Round 1: hi x b_hi (9 distinct accumulators)
#pragma unroll
                for (int n = 0; n < 3; ++n)
                    mma_bf16(acc[0 + n], a0h.x, a0h.y, a0h.z, a0h.w, w0[n].x, w0[n].y);
#pragma unroll
                for (int n = 0; n < 3; ++n)
                    mma_bf16(acc[3 + n], a1h.x, a1h.y, a1h.z, a1h.w, w1[n].x, w1[n].y);
#pragma unroll
                for (int n = 0; n < 3; ++n)
                    mma_bf16(acc[6 + n], a0h.x, a0h.y, a0h.z, a0h.w, w2[n].x, w2[n].y);
                // Round 2: hi x b_lo
#pragma unroll
                for (int n = 0; n < 3; ++n)
                    mma_bf16(acc[0 + n], a0h.x, a0h.y, a0h.z, a0h.w, w0[n].z, w0[n].w);
#pragma unroll
                for (int n = 0; n < 3; ++n)
                    mma_bf16(acc[3 + n], a1h.x, a1h.y, a1h.z, a1h.w, w1[n].z, w1[n].w);
#pragma unroll
                for (int n = 0; n < 3; ++n)
                    mma_bf16(acc[6 + n], a0h.x, a0h.y, a0h.z, a0h.w, w2[n].z, w2[n].w);
                // Round 3: lo x b_hi
#pragma unroll
                for (int n = 0; n < 3; ++n)
                    mma_bf16(acc[0 + n], a0l.x, a0l.y, a0l.z, a0l.w, w0[n].x, w0[n].y);
#pragma unroll
                for (int n = 0; n < 3; ++n)
                    mma_bf16(acc[3 + n], a1l.x, a1l.y, a1l.z, a1l.w, w1[n].x, w1[n].y);
#pragma unroll
                for (int n = 0; n < 3; ++n)
                    mma_bf16(acc[6 + n], a0l.x, a0l.y, a0l.z, a0l.w, w2[n].x, w2[n].y);
            }
        }

        // Layer-0 update -> h0[i]; publish frags + counter.
        // WAR-safe: the per-ks polls above collectively certified all peers
        // (gb,*,w) completed iteration i-1 (same certification as R15's
        // up-front poll, observed incrementally).
        if (i < T) {
#pragma unroll
            for (int p = 0; p < 4; ++p) {
                int jc = 2 * c + (p & 1);
                float rr = fsig(xp[p]     + sBi0[jc]      + acc[0][p] + sBh0[jc]);
                float zz = fsig(xp[4 + p] + sBi0[8 + jc]  + acc[1][p] + sBh0[8 + jc]);
                float nn = ftanh_(xp[8 + p] + sBi0[16 + jc]
                                  + rr * (acc[2][p] + sBh0[16 + jc]));
                h0reg[p] = (1.0f - zz) * nn + zz * h0reg[p];
            }
            unsigned hi01, lo01, hi23, lo23;
            split2(h0reg[0], h0reg[1], hi01, lo01);
            split2(h0reg[2], h0reg[3], hi23, lo23);
            char* bh = (char*)(g_hA0 + ha_idx(bufW, gb, w, ksW, 0, l)) + wboff;
            char* bl = (char*)(g_hA0 + ha_idx(bufW, gb, w, ksW, 1, l)) + wboff;
            __stcg((unsigned long long*)bh, ((unsigned long long)hi23 << 32) | hi01);
            __stcg((unsigned long long*)bl, ((unsigned long long)lo23 << 32) | lo01);
            publish_cnt(myCnt0, l);
        }

        // Layer-1 update -> h1[i-1]; publish frags + counter.
        if (i >= 1) {
#pragma unroll
            for (int p = 0; p < 4; ++p) {
                int jc = 2 * c + (p & 1);
                float rr = fsig(acc[6][p] + sBi1[jc]     + acc[3][p] + sBh1[jc]);
                float zz = fsig(acc[7][p] + sBi1[8 + jc] + acc[4][p] + sBh1[8 + jc]);
                float nn = ftanh_(acc[8][p] + sBi1[16 + jc]
                                  + rr * (acc[5][p] + sBh1[16 + jc]));
                h1reg[p] = (1.0f - zz) * nn + zz * h1reg[p];
            }
            unsigned hi01, lo01, hi23, lo23;
            split2(h1reg[0], h1reg[1], hi01, lo01);
            split2(h1reg[2], h1reg[3], hi23, lo23);
            char* bh = (char*)(g_hA1 + ha_idx(bufW, gb, w, ksW, 0, l)) + wboff;
            char* bl = (char*)(g_hA1 + ha_idx(bufW, gb, w, ksW, 1, l)) + wboff;
            __stcg((unsigned long long*)bh, ((unsigned long long)hi23 << 32) | hi01);
            __stcg((unsigned long long*)bl, ((unsigned long long)lo23 << 32) | lo01);
            publish_cnt(myCnt1, l);

            if (i == T) {
#pragma unroll
                for (int p = 0; p < 4; ++p) {
                    int row = gb0 + w * 16 + g + 8 * (p >> 1);
                    int col = c0 + 2 * c + (p & 1);
                    __stcg(&g_hfin[(size_t)row * H + col], h1reg[p]);
                }
            }
        }
    }

    // Epilogue needs h1 across all groups.
    barrier_sync(&g_cnt_all, &g_gen_all, NCTA);

    // ---- logits + softmax, one warp per batch row ----
    int gw = blockIdx.x * (NTHREADS / 32) + w;
    if (gw < B) {
        const float* hrow = g_hfin + (size_t)gw * H;
        float hk[8];
#pragma unroll
        for (int j2 = 0; j2 < 8; ++j2) hk[j2] = __ldcg(&hrow[l + 32 * j2]);

        float logits[OUT];
#pragma unroll
        for (int o = 0; o < OUT; ++o) {
            float p = 0.0f;
#pragma unroll
            for (int j2 = 0; j2 < 8; ++j2)
                p += hk[j2] * __ldg(&W_out[o * H + l + 32 * j2]);
#pragma unroll
            for (int s = 16; s > 0; s >>= 1)
                p += __shfl_xor_sync(0xffffffffu, p, s);
            logits[o] = p + __ldg(&b_out[o]);
        }
        float mx = logits[0];
#pragma unroll
        for (int o = 1; o < OUT; ++o) mx = fmaxf(mx, logits[o]);
        float sum = 0.0f;
#pragma unroll
        for (int o = 0; o < OUT; ++o) { logits[o] = expf(logits[o] - mx); sum += logits[o]; }
        float inv = 1.0f / sum;
        if (l == 0) {
#pragma unroll
            for (int o = 0; o < OUT; ++o)
                out[(size_t)gw * OUT + o] = logits[o] * inv;
        }
    }
}

extern "C" void kernel_launch(void* const* d_in, const int* in_sizes, int n_in,
                              void* d_out, int out_size) {
    const float* x      = (const float*)d_in[0];
    // d_in[1] = times (unused), d_in[2] = interpolation_method (unused)
    const float* W_ih0  = (const float*)d_in[3];
    const float* W_hh0  = (const float*)d_in[4];
    const float* b_ih0  = (const float*)d_in[5];
    const float* b_hh0  = (const float*)d_in[6];
    const float* W_ih1  = (const float*)d_in[7];
    const float* W_hh1  = (const float*)d_in[8];
    const float* b_ih1  = (const float*)d_in[9];
    const float* b_hh1  = (const float*)d_in[10];
    const float* W_out  = (const float*)d_in[11];
    const float* b_out  = (const float*)d_in[12];
    float* out = (float*)d_out;

    const size_t smem_bytes = (size_t)NWB * 16
        + (size_t)(8 * 192 + 24 * 12 + 4 * 24) * sizeof(float);   // ~80 KB
    cudaFuncSetAttribute(gru_tc_kernel,
                         cudaFuncAttributeMaxDynamicSharedMemorySize, (int)smem_bytes);

    gru_tc_kernel<<<NCTA, NTHREADS, smem_bytes>>>(
        x, W_ih0, W_hh0, b_ih0, b_hh0,
        W_ih1, W_hh1, b_ih1, b_hh1,
        W_out, b_out, out);
}

// round 17
// speedup vs baseline: 1.4778x; 1.4778x over previous
#include <cuda_runtime.h>
#include <cuda_bf16.h>
#include <math.h>

// Problem constants
#define B    512
#define T    365
#define INP  10
#define H    256
#define OUT  20

// 8 batch groups (64 rows) x 32 column groups (8 cols) = 256 persistent CTAs,
// 128 thr = 4 warps; warp w = M-tile (16 rows). Two co-resident CTAs per SM
// (different batch groups -> independent chains; latency overlap).
// R15 mma stream: 9 chains, product-round interleaved, depth-2 LDG pipeline,
// single up-front poll per iteration (warp-granular counters, no barriers).
#define GB        8
#define GC        32
#define NCTA      (GB * GC)
#define NTHREADS  128

// A-fragment arrays: [buf2][gb8][mtile4][kstep16][split2][lane32] x uint4
#define HA_ELEMS  (2 * 8 * 4 * 16 * 2 * 32)

__device__ uint4 g_hA0[HA_ELEMS];
__device__ uint4 g_hA1[HA_ELEMS];
__device__ float g_hfin[B * H];
// Publish counters: [gb][mt][16 ks + 16 pad] -> one 128B line per (gb,mt).
__device__ __align__(128) unsigned g_cnt0[GB][4][32];
__device__ __align__(128) unsigned g_cnt1[GB][4][32];
__device__ unsigned g_cnt_all;
__device__ unsigned g_gen_all;

__device__ __forceinline__ int ha_idx(int buf, int gb, int mt, int ks, int sp, int l) {
    return (((((buf * 8 + gb) * 4 + mt) * 16 + ks) * 2 + sp) * 32 + l);
}

__device__ __forceinline__ void barrier_sync(unsigned* cnt, unsigned* gen, unsigned target) {
    __threadfence();
    __syncthreads();
    if (threadIdx.x == 0) {
        unsigned g = *(volatile unsigned*)gen;
        if (atomicAdd(cnt, 1u) == target - 1u) {
            *cnt = 0u;
            __threadfence();
            atomicAdd(gen, 1u);
        } else {
            while (*(volatile unsigned*)gen == g) { }
        }
    }
    __syncthreads();
}

// All-lane poll: lane l watches counter (l&15); pass when all 16 >= target.
__device__ __forceinline__ void poll16(const unsigned* cb, unsigned target, int l) {
    const unsigned* p = cb + (l & 15);
    unsigned v;
    do {
        asm volatile("ld.acquire.gpu.global.u32 %0, [%1];" : "=r"(v) : "l"(p) : "memory");
    } while (!__all_sync(0xffffffffu, v >= target));
}

// Producer publish: fence own stores, warp-converge, lane0 RED +1.
__device__ __forceinline__ void publish_cnt(unsigned* cnt, int l) {
    __threadfence();
    __syncwarp();
    if (l == 0) atomicAdd(cnt, 1u);
}

// mma.sync m16n8k16 row.col f32.bf16.bf16.f32, accumulate in place.
__device__ __forceinline__ void mma_bf16(float* d, unsigned a0, unsigned a1,
                                         unsigned a2, unsigned a3,
                                         unsigned b0, unsigned b1) {
    asm volatile(
        "mma.sync.aligned.m16n8k16.row.col.f32.bf16.bf16.f32 "
        "{%0,%1,%2,%3}, {%4,%5,%6,%7}, {%8,%9}, {%0,%1,%2,%3};"
        : "+f"(d[0]), "+f"(d[1]), "+f"(d[2]), "+f"(d[3])
        : "r"(a0), "r"(a1), "r"(a2), "r"(a3), "r"(b0), "r"(b1));
}

// Split two fp32 into packed bf16x2 (hi) + packed bf16x2 (lo residual).
__device__ __forceinline__ void split2(float a, float b, unsigned& hi, unsigned& lo) {
    __nv_bfloat16 ah = __float2bfloat16_rn(a), bh = __float2bfloat16_rn(b);
    __nv_bfloat16 al = __float2bfloat16_rn(a - __bfloat162float(ah));
    __nv_bfloat16 bl = __float2bfloat16_rn(b - __bfloat162float(bh));
    __nv_bfloat162 h2; h2.x = ah; h2.y = bh;
    __nv_bfloat162 l2; l2.x = al; l2.y = bl;
    hi = *reinterpret_cast<unsigned*>(&h2);
    lo = *reinterpret_cast<unsigned*>(&l2);
}

// Fast gate math (MUFU-based; ~1e-6 error vs 1e-3 tolerance).
__device__ __forceinline__ float fsig(float v) {
    return 1.0f / (1.0f + __expf(-v));
}
__device__ __forceinline__ float ftanh_(float v) {
    return 2.0f / (1.0f + __expf(-2.0f * v)) - 1.0f;
}

// Weight frags: sets s (0=hh0, 1=hh1, 2=ih1) x 3 ntiles x 16 ksteps x 32 lanes,
// uint4 = {b0_hi, b1_hi, b0_lo, b1_lo}. 4608 x 16B = 72 KB per CTA.
#define NWB (3 * 3 * 16 * 32)

__global__ void __launch_bounds__(NTHREADS, 2)
gru_tc_kernel(const float* __restrict__ x,
              const float* __restrict__ W_ih0, const float* __restrict__ W_hh0,
              const float* __restrict__ b_ih0, const float* __restrict__ b_hh0,
              const float* __restrict__ W_ih1, const float* __restrict__ W_hh1,
              const float* __restrict__ b_ih1, const float* __restrict__ b_hh1,
              const float* __restrict__ W_out, const float* __restrict__ b_out,
              float* __restrict__ out) {
    extern __shared__ char smraw[];
    uint4* sWB  = reinterpret_cast<uint4*>(smraw);     // NWB x 16B
    float* sx   = reinterpret_cast<float*>(sWB + NWB); // 4 warps x 192
    float* sWi0 = sx + 4 * 192;                        // 24*12
    float* sBi0 = sWi0 + 24 * 12;                      // 24 each
    float* sBh0 = sBi0 + 24;
    float* sBi1 = sBh0 + 24;
    float* sBh1 = sBi1 + 24;

    const int tid = threadIdx.x;
    const int w   = tid >> 5;              // warp = M-tile 0..3
    const int l   = tid & 31;              // lane
    const int g   = l >> 2;                // frag row group 0..7
    const int c   = l & 3;                 // frag col pair 0..3
    const int gb  = blockIdx.x >> 5;       // batch group 0..7
    const int gc  = blockIdx.x & 31;       // column group
    const int c0  = gc * 8;
    const int gb0 = gb * 64;
    const int ksW = gc >> 1;               // kstep our h-cols land in
    const int wboff = 8 * (gc & 1);        // byte offset within 16B frag slot

    unsigned* myCnt0 = &g_cnt0[gb][w][ksW];
    unsigned* myCnt1 = &g_cnt1[gb][w][ksW];
    const unsigned* pollC0 = &g_cnt0[gb][w][0];
    const unsigned* pollC1 = &g_cnt1[gb][w][0];

    // ---- Prologue: pack weights into B-fragment layout (hi/lo split) ----
    {
        const float* Wsets[3] = { W_hh0, W_hh1, W_ih1 };
        for (int e = tid; e < NWB; e += NTHREADS) {
            int lane = e & 31;
            int ks   = (e >> 5) & 15;
            int rest = e >> 9;
            int n    = rest % 3;
            int s    = rest / 3;
            int t4 = lane & 3, nn = lane >> 2;
            const float* Wp = Wsets[s] + (size_t)(n * H + c0 + nn) * H + ks * 16;
            float w00 = Wp[2 * t4],     w01 = Wp[2 * t4 + 1];
            float w10 = Wp[8 + 2 * t4], w11 = Wp[9 + 2 * t4];
            uint4 v;
            split2(w00, w01, v.x, v.z);
            split2(w10, w11, v.y, v.w);
            sWB[e] = v;
        }
    }
    for (int idx = tid; idx < 24 * INP; idx += NTHREADS) {
        int row = idx / INP, i = idx - row * INP;
        int gg = row >> 3, j = row & 7;
        sWi0[row * 12 + i] = W_ih0[(gg * H + c0 + j) * INP + i];
    }
    if (tid < 24) {
        int gg = tid >> 3, j = tid & 7;
        int grow = gg * H + c0 + j;
        sBi0[tid] = b_ih0[grow];
        sBh0[tid] = b_hh0[grow];
        sBi1[tid] = b_ih1[grow];
        sBh1[tid] = b_hh1[grow];
    }

    // Zero A-frag buffers + counters; every launch (determinism).
    {
        uint4 z4 = make_uint4(0u, 0u, 0u, 0u);
        for (int i = blockIdx.x * NTHREADS + tid; i < HA_ELEMS; i += NCTA * NTHREADS) {
            g_hA0[i] = z4;
            g_hA1[i] = z4;
        }
        unsigned* c0p = &g_cnt0[0][0][0];
        unsigned* c1p = &g_cnt1[0][0][0];
        for (int i = blockIdx.x * NTHREADS + tid; i < GB * 4 * 32; i += NCTA * NTHREADS) {
            c0p[i] = 0u;
            c1p[i] = 0u;
        }
    }
    barrier_sync(&g_cnt_all, &g_gen_all, NCTA);

    // Per-thread persistent hidden state (4 D-frag positions).
    float h0reg[4] = {0.f, 0.f, 0.f, 0.f};
    float h1reg[4] = {0.f, 0.f, 0.f, 0.f};

    // ---- Warp-autonomous loop: iter i computes h0[i] and h1[i-1]. ----
    for (int i = 0; i <= T; ++i) {
        const int bufR = i & 1, bufW = bufR ^ 1;

        // Stage x[i] + x-projection BEFORE polls (h-independent).
        float xp[12];
        if (i < T) {
            float* sxw = sx + w * 192;
            for (int e = l; e < 16 * INP; e += 32) {
                int row = e / INP, k = e - row * INP;
                sxw[row * 12 + k] =
                    __ldg(&x[((size_t)(gb0 + w * 16 + row) * T + i) * INP + k]);
            }
            __syncwarp();
#pragma unroll
            for (int p = 0; p < 4; ++p) {
                int lrow = g + 8 * (p >> 1);
                int jc = 2 * c + (p & 1);
                float xr = 0.f, xz = 0.f, xn = 0.f;
#pragma unroll
                for (int k = 0; k < INP; ++k) {
                    float xv = sxw[lrow * 12 + k];
                    xr += xv * sWi0[(0 * 8 + jc) * 12 + k];
                    xz += xv * sWi0[(1 * 8 + jc) * 12 + k];
                    xn += xv * sWi0[(2 * 8 + jc) * 12 + k];
                }
                xp[p] = xr; xp[4 + p] = xz; xp[8 + p] = xn;
            }
        }

        // RAW gates up front: h0[i-1] frags present; h1[i-2] frags present.
        poll16(pollC0, 2u * (unsigned)i, l);
        if (i >= 1) poll16(pollC1, 2u * (unsigned)(i - 1), l);

        // ===== Single merged mma stream: 9 chains, product-round interleaved.
        // acc [0..2]=hh0, [3..5]=hh1, [6..8]=ih1. Same-acc distance = 9 mma.
        float acc[9][4] = {};
        {
            const uint4* pA0 = g_hA0 + ha_idx(bufR, gb, w, 0, 0, 0);
            const uint4* pA1 = g_hA1 + ha_idx(bufR, gb, w, 0, 0, 0);
            // Depth-2 LDG pipeline, 3-slot register ring.
            uint4 rA0h[3], rA0l[3], rA1h[3], rA1l[3];
#pragma unroll
            for (int pld = 0; pld < 2; ++pld) {
                rA0h[pld] = __ldcg(pA0 + pld * 64 + l);
                rA0l[pld] = __ldcg(pA0 + pld * 64 + 32 + l);
                rA1h[pld] = __ldcg(pA1 + pld * 64 + l);
                rA1l[pld] = __ldcg(pA1 + pld * 64 + 32 + l);
            }
#pragma unroll
            for (int ks = 0; ks < 16; ++ks) {
                const int cur = ks % 3;
                if (ks + 2 < 16) {
                    const int nx = (ks + 2) % 3;
                    rA0h[nx] = __ldcg(pA0 + (ks + 2) * 64 + l);
                    rA0l[nx] = __ldcg(pA0 + (ks + 2) * 64 + 32 + l);
                    rA1h[nx] = __ldcg(pA1 + (ks + 2) * 64 + l);
                    rA1l[nx] = __ldcg(pA1 + (ks + 2) * 64 + 32 + l);
                }
                uint4 w0[3], w1[3], w2[3];
#pragma unroll
                for (int n = 0; n < 3; ++n) {
                    w0[n] = sWB[((0 * 3 + n) * 16 + ks) * 32 + l];
                    w1[n] = sWB[((1 * 3 + n) * 16 + ks) * 32 + l];
                    w2[n] = sWB[((2 * 3 + n) * 16 + ks) * 32 + l];
                }
                const uint4 a0h = rA0h[cur], a0l = rA0l[cur];
                const uint4 a1h = rA1h[cur], a1l = rA1l[cur];
                // Round 1: hi x b_hi (9 distinct accumulators)
#pragma unroll
                for (int n = 0; n < 3; ++n)
                    mma_bf16(acc[0 + n], a0h.x, a0h.y, a0h.z, a0h.w, w0[n].x, w0[n].y);
#pragma unroll
                for (int n = 0; n < 3; ++n)
                    mma_bf16(acc[3 + n], a1h.x, a1h.y, a1h.z, a1h.w, w1[n].x, w1[n].y);
#pragma unroll
                for (int n = 0; n < 3; ++n)
                    mma_bf16(acc[6 + n], a0h.x, a0h.y, a0h.z, a0h.w, w2[n].x, w2[n].y);
                // Round 2: hi x b_lo
#pragma unroll
                for (int n = 0; n < 3; ++n)
                    mma_bf16(acc[0 + n], a0h.x, a0h.y, a0h.z, a0h.w, w0[n].z, w0[n].w);
#pragma unroll
                for (int n = 0; n < 3; ++n)
                    mma_bf16(acc[3 + n], a1h.x, a1h.y, a1h.z, a1h.w, w1[n].z, w1[n].w);
#pragma unroll
                for (int n = 0; n < 3; ++n)
                    mma_bf16(acc[6 + n], a0h.x, a0h.y, a0h.z, a0h.w, w2[n].z, w2[n].w);
                // Round 3: lo x b_hi
#pragma unroll
                for (int n = 0; n < 3; ++n)
                    mma_bf16(acc[0 + n], a0l.x, a0l.y, a0l.z, a0l.w, w0[n].x, w0[n].y);
#pragma unroll
                for (int n = 0; n < 3; ++n)
                    mma_bf16(acc[3 + n], a1l.x, a1l.y, a1l.z, a1l.w, w1[n].x, w1[n].y);
#pragma unroll
                for (int n = 0; n < 3; ++n)
                    mma_bf16(acc[6 + n], a0l.x, a0l.y, a0l.z, a0l.w, w2[n].x, w2[n].y);
            }
        }

        // Layer-0 update -> h0[i]; publish frags + counter.
        if (i < T) {
#pragma unroll
            for (int p = 0; p < 4; ++p) {
                int jc = 2 * c + (p & 1);
                float rr = fsig(xp[p]     + sBi0[jc]      + acc[0][p] + sBh0[jc]);
                float zz = fsig(xp[4 + p] + sBi0[8 + jc]  + acc[1][p] + sBh0[8 + jc]);
                float nn = ftanh_(xp[8 + p] + sBi0[16 + jc]
                                  + rr * (acc[2][p] + sBh0[16 + jc]));
                h0reg[p] = (1.0f - zz) * nn + zz * h0reg[p];
            }
            unsigned hi01, lo01, hi23, lo23;
            split2(h0reg[0], h0reg[1], hi01, lo01);
            split2(h0reg[2], h0reg[3], hi23, lo23);
            char* bh = (char*)(g_hA0 + ha_idx(bufW, gb, w, ksW, 0, l)) + wboff;
            char* bl = (char*)(g_hA0 + ha_idx(bufW, gb, w, ksW, 1, l)) + wboff;
            __stcg((unsigned long long*)bh, ((unsigned long long)hi23 << 32) | hi01);
            __stcg((unsigned long long*)bl, ((unsigned long long)lo23 << 32) | lo01);
            publish_cnt(myCnt0, l);
        }

        // Layer-1 update -> h1[i-1]; publish frags + counter.
        if (i >= 1) {
#pragma unroll
            for (int p = 0; p < 4; ++p) {
                int jc = 2 * c + (p & 1);
                float rr = fsig(acc[6][p] + sBi1[jc]     + acc[3][p] + sBh1[jc]);
                float zz = fsig(acc[7][p] + sBi1[8 + jc] + acc[4][p] + sBh1[8 + jc]);
                float nn = ftanh_(acc[8][p] + sBi1[16 + jc]
                                  + rr * (acc[5][p] + sBh1[16 + jc]));
                h1reg[p] = (1.0f - zz) * nn + zz * h1reg[p];
            }
            unsigned hi01, lo01, hi23, lo23;
            split2(h1reg[0], h1reg[1], hi01, lo01);
            split2(h1reg[2], h1reg[3], hi23, lo23);
            char* bh = (char*)(g_hA1 + ha_idx(bufW, gb, w, ksW, 0, l)) + wboff;
            char* bl = (char*)(g_hA1 + ha_idx(bufW, gb, w, ksW, 1, l)) + wboff;
            __stcg((unsigned long long*)bh, ((unsigned long long)hi23 << 32) | hi01);
            __stcg((unsigned long long*)bl, ((unsigned long long)lo23 << 32) | lo01);
            publish_cnt(myCnt1, l);

            if (i == T) {
#pragma unroll
                for (int p = 0; p < 4; ++p) {
                    int row = gb0 + w * 16 + g + 8 * (p >> 1);
                    int col = c0 + 2 * c + (p & 1);
                    __stcg(&g_hfin[(size_t)row * H + col], h1reg[p]);
                }
            }
        }
    }

    // Epilogue needs h1 across all groups.
    barrier_sync(&g_cnt_all, &g_gen_all, NCTA);

    // ---- logits + softmax, one warp per batch row ----
    int gw = blockIdx.x * (NTHREADS / 32) + w;
    if (gw < B) {
        const float* hrow = g_hfin + (size_t)gw * H;
        float hk[8];
#pragma unroll
        for (int j2 = 0; j2 < 8; ++j2) hk[j2] = __ldcg(&hrow[l + 32 * j2]);

        float logits[OUT];
#pragma unroll
        for (int o = 0; o < OUT; ++o) {
            float p = 0.0f;
#pragma unroll
            for (int j2 = 0; j2 < 8; ++j2)
                p += hk[j2] * __ldg(&W_out[o * H + l + 32 * j2]);
#pragma unroll
            for (int s = 16; s > 0; s >>= 1)
                p += __shfl_xor_sync(0xffffffffu, p, s);
            logits[o] = p + __ldg(&b_out[o]);
        }
        float mx = logits[0];
#pragma unroll
        for (int o = 1; o < OUT; ++o) mx = fmaxf(mx, logits[o]);
        float sum = 0.0f;
#pragma unroll
        for (int o = 0; o < OUT; ++o) { logits[o] = expf(logits[o] - mx); sum += logits[o]; }
        float inv = 1.0f / sum;
        if (l == 0) {
#pragma unroll
            for (int o = 0; o < OUT; ++o)
                out[(size_t)gw * OUT + o] = logits[o] * inv;
        }
    }
}

extern "C" void kernel_launch(void* const* d_in, const int* in_sizes, int n_in,
                              void* d_out, int out_size) {
    const float* x      = (const float*)d_in[0];
    // d_in[1] = times (unused), d_in[2] = interpolation_method (unused)
    const float* W_ih0  = (const float*)d_in[3];
    const float* W_hh0  = (const float*)d_in[4];
    const float* b_ih0  = (const float*)d_in[5];
    const float* b_hh0  = (const float*)d_in[6];
    const float* W_ih1  = (const float*)d_in[7];
    const float* W_hh1  = (const float*)d_in[8];
    const float* b_ih1  = (const float*)d_in[9];
    const float* b_hh1  = (const float*)d_in[10];
    const float* W_out  = (const float*)d_in[11];
    const float* b_out  = (const float*)d_in[12];
    float* out = (float*)d_out;

    const size_t smem_bytes = (size_t)NWB * 16
        + (size_t)(4 * 192 + 24 * 12 + 4 * 24) * sizeof(float);   // ~77.5 KB
    cudaFuncSetAttribute(gru_tc_kernel,
                         cudaFuncAttributeMaxDynamicSharedMemorySize, (int)smem_bytes);

    gru_tc_kernel<<<NCTA, NTHREADS, smem_bytes>>>(
        x, W_ih0, W_hh0, b_ih0, b_hh0,
        W_ih1, W_hh1, b_ih1, b_hh1,
        W_out, b_out, out);
}